// round 2
// baseline (speedup 1.0000x reference)
#include <cuda_runtime.h>
#include <cuda_bf16.h>
#include <math.h>

// ------------------------- problem constants -------------------------
#define BB   512
#define NN   64
#define KK   16
#define ROWS (BB*NN)          // 32768
#define EPSV 1e-5f

// ------------------------- scratch (device globals) ------------------
__device__ float g_h0[ROWS*64];
__device__ float g_h1[ROWS*64];
__device__ float g_h2[ROWS*128];
__device__ float g_h3[ROWS*256];
__device__ float g_Abuf[ROWS*256];
__device__ float g_Bbuf[ROWS*256];
__device__ float g_Obuf[ROWS*256];
__device__ int   g_idxbuf[ROWS*KK];
__device__ float g_pool[BB*896];
__device__ float g_z1[BB*512];
__device__ float g_z2[BB*256];
__device__ float g_stats[4096];
__device__ float g_ss[4096];

// stage bases in g_stats/g_ss
#define ST0 0      // pre0   C=64
#define ST1 128    // c1 pre1 C=64
#define ST2 256    // c1 pre2 C=64
#define ST3 384    // c2 pre1 C=128
#define ST4 640    // c2 pre2 C=128
#define ST5 896    // c3 pre1 C=256
#define ST6 1408   // c3 pre2 C=256
#define ST7 1920   // zc1 C=512
#define ST8 2944   // zc2 C=256

__device__ __forceinline__ unsigned enc_f(float f) {
    unsigned u = __float_as_uint(f);
    return (u & 0x80000000u) ? ~u : (u | 0x80000000u);
}
__device__ __forceinline__ float dec_f(unsigned u) {
    return (u & 0x80000000u) ? __uint_as_float(u ^ 0x80000000u) : __uint_as_float(~u);
}
#define NEG_INF __int_as_float(0xff800000)

// ------------------------- kernels -----------------------------------

__global__ void k_zero_stats(float* stats) {
    for (int i = threadIdx.x; i < 4096; i += blockDim.x) stats[i] = 0.f;
}

// pre0 = x @ w_in  (32768x6 @ 6x64) + per-channel stats
__global__ void k_in_gemm(const float* __restrict__ x, const float* __restrict__ w,
                          float* __restrict__ pre, float* __restrict__ stats) {
    __shared__ float xs[128*6];
    __shared__ float wsm[6*64];
    __shared__ float red[4][64];
    int t = threadIdx.x;
    int r0 = blockIdx.x * 128;
    for (int e = t; e < 768; e += 256) xs[e] = x[r0*6 + e];
    for (int e = t; e < 384; e += 256) wsm[e] = w[e];   // FIXED: was `if (t < 384)` with 256 threads
    __syncthreads();
    int m = t & 63, rg = t >> 6;
    float s = 0.f, s2 = 0.f;
    for (int r = rg; r < 128; r += 4) {
        float v = 0.f;
        #pragma unroll
        for (int k = 0; k < 6; k++) v += xs[r*6+k] * wsm[k*64+m];
        pre[(r0 + r)*64 + m] = v;
        s += v; s2 += v*v;
    }
    red[rg][m] = s; __syncthreads();
    if (rg == 0) atomicAdd(&stats[ST0 + m], red[0][m]+red[1][m]+red[2][m]+red[3][m]);
    __syncthreads();
    red[rg][m] = s2; __syncthreads();
    if (rg == 0) atomicAdd(&stats[ST0 + 64 + m], red[0][m]+red[1][m]+red[2][m]+red[3][m]);
}

__global__ void k_finalize(const float* __restrict__ stats, float* __restrict__ ss,
                           int base, int C, float invcnt,
                           const float* __restrict__ g, const float* __restrict__ b) {
    int c = blockIdx.x*blockDim.x + threadIdx.x;
    if (c >= C) return;
    float mean = stats[base + c] * invcnt;
    float var  = stats[base + C + c] * invcnt - mean*mean;
    float sc = g[c] * rsqrtf(var + EPSV);
    ss[base + c]     = sc;
    ss[base + C + c] = b[c] - mean*sc;
}

// in-place: buf = lrelu(sc*buf + sh)
__global__ void k_apply(float* __restrict__ buf, const float* __restrict__ ss,
                        int base, int C, int total) {
    int i = blockIdx.x*blockDim.x + threadIdx.x;
    if (i >= total) return;
    int c = i & (C-1);
    float v = ss[base+c]*buf[i] + ss[base+C+c];
    buf[i] = v > 0.f ? v : 0.2f*v;
}

// edge-conv epilogue: H = (O==-inf) ? 0 : lrelu(sc*O+sh)
__global__ void k_apply_ec(const float* __restrict__ O, float* __restrict__ H,
                           const float* __restrict__ ss, int base, int C, int total) {
    int i = blockIdx.x*blockDim.x + threadIdx.x;
    if (i >= total) return;
    int c = i & (C-1);
    float v = O[i];
    float r;
    if (v == NEG_INF) r = 0.f;
    else { float z = ss[base+c]*v + ss[base+C+c]; r = z > 0.f ? z : 0.2f*z; }
    H[i] = r;
}

// ----- E1: per-batch KNN + A/B factor GEMMs + pre1 stats -----
template<int C_IN, int C_MID>
__global__ void k_e1(const float* __restrict__ X, const float* __restrict__ w_a,
                     float* __restrict__ gA, float* __restrict__ gB,
                     int* __restrict__ gidx, float* __restrict__ stats, int sbase)
{
    extern __shared__ float sm[];
    const int XST = C_IN + 1;
    float* Xs = sm;                         // 64*XST
    float* sq = Xs + 64*XST;                // 64
    float* As = sq + 64;                    // 64*C_MID
    float* Bs = As + 64*C_MID;              // 64*C_MID
    int*   idx_s = (int*)(Bs + 64*C_MID);   // 1024

    int b = blockIdx.x;
    int t = threadIdx.x;
    const float* Xb = X + (size_t)b*64*C_IN;

    for (int e = t; e < 64*C_IN; e += 256) {
        int i = e / C_IN, k = e % C_IN;
        Xs[i*XST + k] = Xb[e];
    }
    __syncthreads();
    if (t < 64) {
        float s = 0.f;
        for (int k = 0; k < C_IN; k++) { float v = Xs[t*XST+k]; s += v*v; }
        sq[t] = s;
    }
    __syncthreads();

    // KNN: warp per row, iterative argmin with stable (d, index) tie-break
    {
        int w = t >> 5, l = t & 31;
        for (int i = w; i < 64; i += 8) {
            float d0 = 0.f, d1 = 0.f;
            for (int k = 0; k < C_IN; k++) {
                float xi = Xs[i*XST+k];
                d0 += xi * Xs[l*XST+k];
                d1 += xi * Xs[(l+32)*XST+k];
            }
            float my0 = sq[i] + sq[l]    - 2.f*d0;
            float my1 = sq[i] + sq[l+32] - 2.f*d1;
            for (int pick = 0; pick <= KK; pick++) {
                float dm; int jm;
                if (my0 <= my1) { dm = my0; jm = l; } else { dm = my1; jm = l+32; }
                #pragma unroll
                for (int off = 16; off; off >>= 1) {
                    float od = __shfl_xor_sync(0xffffffffu, dm, off);
                    int   oj = __shfl_xor_sync(0xffffffffu, jm, off);
                    if (od < dm || (od == dm && oj < jm)) { dm = od; jm = oj; }
                }
                if ((jm & 31) == l) { if (jm >= 32) my1 = __int_as_float(0x7f800000); else my0 = __int_as_float(0x7f800000); }
                if (pick > 0 && l == 0) {
                    idx_s[i*KK + pick - 1] = jm;
                    gidx[((size_t)b*64 + i)*KK + pick - 1] = jm;
                }
            }
        }
    }
    __syncthreads();

    // A = X@Wd, B = X@(Wn-Wd)
    {
        const int G = 256 / C_MID;
        const int IPG = 64 / G;
        int m = t % C_MID;
        int g = t / C_MID;
        for (int i0 = g*IPG; i0 < (g+1)*IPG; i0 += 8) {
            float aa[8], bb[8];
            #pragma unroll
            for (int ii = 0; ii < 8; ii++) { aa[ii]=0.f; bb[ii]=0.f; }
            for (int k = 0; k < C_IN; k++) {
                float wn  = w_a[k*C_MID + m];
                float wd  = w_a[(C_IN + k)*C_MID + m];
                float wnd = wn - wd;
                #pragma unroll
                for (int ii = 0; ii < 8; ii++) {
                    float xv = Xs[(i0+ii)*XST + k];
                    aa[ii] += xv * wd;
                    bb[ii] += xv * wnd;
                }
            }
            #pragma unroll
            for (int ii = 0; ii < 8; ii++) {
                As[(i0+ii)*C_MID + m] = aa[ii];
                Bs[(i0+ii)*C_MID + m] = bb[ii];
                gA[((size_t)b*64 + i0+ii)*C_MID + m] = aa[ii];
                gB[((size_t)b*64 + i0+ii)*C_MID + m] = bb[ii];
            }
        }
    }
    __syncthreads();

    // stats of pre1 = A[c] + B[idx[c,k]]
    {
        const int G = 256 / C_MID;
        int m = t % C_MID, rep = t / C_MID;
        float s = 0.f, s2 = 0.f;
        for (int r = rep; r < 64*KK; r += G) {
            int c = r >> 4;
            int nbr = idx_s[r];
            float v = As[c*C_MID + m] + Bs[nbr*C_MID + m];
            s += v; s2 += v*v;
        }
        atomicAdd(&stats[sbase + m], s);
        atomicAdd(&stats[sbase + C_MID + m], s2);
    }
}

// ----- E3: build h rows, GEMM with w_b chunk, scatter-max + pre2 stats -----
template<int C_MID, int C_OUT>
__global__ void k_e3(const float* __restrict__ gA, const float* __restrict__ gB,
                     const int* __restrict__ gidx, const float* __restrict__ w_b,
                     const float* __restrict__ ss, int ssbase,
                     float* __restrict__ stats, int sbase,
                     float* __restrict__ O)
{
    extern __shared__ float sm[];
    const int HST = C_MID + 1;
    float* Ws  = sm;                        // C_MID*64 (float4 aligned)
    float* Hs  = Ws + C_MID*64;             // 32*HST
    float* scs = Hs + 32*HST;               // C_MID
    float* shs = scs + C_MID;               // C_MID
    unsigned* outu = (unsigned*)(shs + C_MID);  // 4096
    int* idx_s = (int*)(outu + 4096);           // 1024

    int b  = blockIdx.x;
    int cb = blockIdx.y * 64;
    int t  = threadIdx.x;

    for (int e = t; e < C_MID*64; e += 256)
        Ws[e] = w_b[(e >> 6)*C_OUT + cb + (e & 63)];
    for (int e = t; e < 1024; e += 256) idx_s[e] = gidx[b*1024 + e];
    for (int e = t; e < C_MID; e += 256) {
        scs[e] = ss[ssbase + e];
        shs[e] = ss[ssbase + C_MID + e];
    }
    for (int e = t; e < 4096; e += 256) outu[e] = 0u;
    __syncthreads();

    const float* Ab = gA + (size_t)b*64*C_MID;
    const float* Bb = gB + (size_t)b*64*C_MID;
    const float4* Ws4 = (const float4*)Ws;

    int cg = t & 15;
    int rg = t >> 4;
    int c0 = cg * 4;
    float csum[4] = {0,0,0,0}, csq[4] = {0,0,0,0};

    for (int tt = 0; tt < 32; tt++) {
        for (int e = t; e < 32*C_MID; e += 256) {
            int rr = e / C_MID, m = e % C_MID;
            int r = tt*32 + rr;
            int c = r >> 4;
            int nbr = idx_s[r];
            float v = Ab[c*C_MID + m] + Bb[nbr*C_MID + m];
            v = scs[m]*v + shs[m];
            Hs[rr*HST + m] = v > 0.f ? v : 0.2f*v;
        }
        __syncthreads();
        int rr0 = rg*2, rr1 = rr0 + 1;
        float a00=0,a01=0,a02=0,a03=0,a10=0,a11=0,a12=0,a13=0;
        for (int kk = 0; kk < C_MID; kk++) {
            float h0 = Hs[rr0*HST + kk];
            float h1 = Hs[rr1*HST + kk];
            float4 wv = Ws4[kk*16 + cg];
            a00 += h0*wv.x; a01 += h0*wv.y; a02 += h0*wv.z; a03 += h0*wv.w;
            a10 += h1*wv.x; a11 += h1*wv.y; a12 += h1*wv.z; a13 += h1*wv.w;
        }
        {
            int r = tt*32 + rr0;
            int n = idx_s[r];
            csum[0]+=a00; csq[0]+=a00*a00; atomicMax(&outu[n*64+c0+0], enc_f(a00));
            csum[1]+=a01; csq[1]+=a01*a01; atomicMax(&outu[n*64+c0+1], enc_f(a01));
            csum[2]+=a02; csq[2]+=a02*a02; atomicMax(&outu[n*64+c0+2], enc_f(a02));
            csum[3]+=a03; csq[3]+=a03*a03; atomicMax(&outu[n*64+c0+3], enc_f(a03));
            r = tt*32 + rr1;
            n = idx_s[r];
            csum[0]+=a10; csq[0]+=a10*a10; atomicMax(&outu[n*64+c0+0], enc_f(a10));
            csum[1]+=a11; csq[1]+=a11*a11; atomicMax(&outu[n*64+c0+1], enc_f(a11));
            csum[2]+=a12; csq[2]+=a12*a12; atomicMax(&outu[n*64+c0+2], enc_f(a12));
            csum[3]+=a13; csq[3]+=a13*a13; atomicMax(&outu[n*64+c0+3], enc_f(a13));
        }
        __syncthreads();
    }
    #pragma unroll
    for (int j = 0; j < 4; j++) {
        atomicAdd(&stats[sbase + cb + c0 + j], csum[j]);
        atomicAdd(&stats[sbase + C_OUT + cb + c0 + j], csq[j]);
    }
    // last in-loop __syncthreads ordered all scatters
    for (int e = t; e < 4096; e += 256) {
        unsigned u = outu[e];
        float v = u ? dec_f(u) : NEG_INF;
        int n = e >> 6, j = e & 63;
        O[((size_t)b*64 + n)*C_OUT + cb + j] = v;
    }
}

// pooled = [mean_n h, max_n h], h = concat(h1,h2,h3)
__global__ void k_pool(const float* __restrict__ h1, const float* __restrict__ h2,
                       const float* __restrict__ h3, float* __restrict__ pool) {
    int b = blockIdx.x, t = threadIdx.x;
    for (int ch = t; ch < 448; ch += 256) {
        const float* src; int C, cc;
        if (ch < 64)       { src = h1; C = 64;  cc = ch; }
        else if (ch < 192) { src = h2; C = 128; cc = ch - 64; }
        else               { src = h3; C = 256; cc = ch - 192; }
        float s = 0.f, mx = NEG_INF;
        for (int n = 0; n < 64; n++) {
            float v = src[((size_t)b*64 + n)*C + cc];
            s += v; mx = fmaxf(mx, v);
        }
        pool[b*896 + ch]       = s * (1.f/64.f);
        pool[b*896 + 448 + ch] = mx;
    }
}

// classifier GEMM (tiled 16x16), optional bias, optional column stats
__global__ void k_gemm(const float* __restrict__ A, const float* __restrict__ W,
                       const float* __restrict__ bias, float* __restrict__ Cout,
                       int M, int Kd, int Nn, float* stats, int sbase) {
    __shared__ float as[16][17], ws[16][17];
    int tx = threadIdx.x, ty = threadIdx.y;
    int row = blockIdx.y*16 + ty;
    int col = blockIdx.x*16 + tx;
    float acc = 0.f;
    for (int k0 = 0; k0 < Kd; k0 += 16) {
        as[ty][tx] = (row < M && k0+tx < Kd) ? A[row*Kd + k0 + tx] : 0.f;
        ws[ty][tx] = (k0+ty < Kd && col < Nn) ? W[(k0+ty)*Nn + col] : 0.f;
        __syncthreads();
        #pragma unroll
        for (int kk = 0; kk < 16; kk++) acc += as[ty][kk]*ws[kk][tx];
        __syncthreads();
    }
    if (row < M && col < Nn) {
        if (bias) acc += bias[col];
        Cout[row*Nn + col] = acc;
        if (stats) {
            atomicAdd(&stats[sbase + col], acc);
            atomicAdd(&stats[sbase + Nn + col], acc*acc);
        }
    }
}

// ------------------------- host launcher -----------------------------
static inline size_t e1_smem(int cin, int cmid) {
    return (size_t)(64*(cin+1) + 64 + 2*64*cmid)*4 + 1024*4;
}
static inline size_t e3_smem(int cmid) {
    return (size_t)(cmid*64 + 32*(cmid+1) + 2*cmid)*4 + 4096*4 + 1024*4;
}

extern "C" void kernel_launch(void* const* d_in, const int* in_sizes, int n_in,
                              void* d_out, int out_size) {
    // input-order detection: reference (dict) order has x (196608 floats) first.
    // Fallback: alphabetical metadata order.
    static const int ALPHA[31] = {30,7,26,17,6,20,11,0,21,12,1,22,13,2,23,14,3,
                                  24,15,4,25,16,5,27,18,8,28,19,9,29,10};
    const void* in[31];
    bool refOrder = (in_sizes[0] == ROWS*6);
    for (int i = 0; i < 31; i++) in[i] = refOrder ? d_in[i] : d_in[ALPHA[i]];

    const float* x    = (const float*)in[0];
    const float* w_in = (const float*)in[2];
    const float* g_in = (const float*)in[3];
    const float* b_in = (const float*)in[4];
    const float* w1a  = (const float*)in[5];
    const float* g1a  = (const float*)in[6];
    const float* b1a  = (const float*)in[7];
    const float* w1b  = (const float*)in[8];
    const float* g1b  = (const float*)in[9];
    const float* b1b  = (const float*)in[10];
    const float* w2a  = (const float*)in[11];
    const float* g2a  = (const float*)in[12];
    const float* b2a  = (const float*)in[13];
    const float* w2b  = (const float*)in[14];
    const float* g2b  = (const float*)in[15];
    const float* b2b  = (const float*)in[16];
    const float* w3a  = (const float*)in[17];
    const float* g3a  = (const float*)in[18];
    const float* b3a  = (const float*)in[19];
    const float* w3b  = (const float*)in[20];
    const float* g3b  = (const float*)in[21];
    const float* b3b  = (const float*)in[22];
    const float* wc1  = (const float*)in[23];
    const float* gc1  = (const float*)in[24];
    const float* bc1  = (const float*)in[25];
    const float* wc2  = (const float*)in[26];
    const float* gc2  = (const float*)in[27];
    const float* bc2  = (const float*)in[28];
    const float* wc3  = (const float*)in[29];
    const float* bc3  = (const float*)in[30];
    float* out = (float*)d_out;

    float *h0, *h1, *h2, *h3, *Abuf, *Bbuf, *Obuf, *pool, *z1, *z2, *stats, *ss;
    int* idxp;
    cudaGetSymbolAddress((void**)&h0, g_h0);
    cudaGetSymbolAddress((void**)&h1, g_h1);
    cudaGetSymbolAddress((void**)&h2, g_h2);
    cudaGetSymbolAddress((void**)&h3, g_h3);
    cudaGetSymbolAddress((void**)&Abuf, g_Abuf);
    cudaGetSymbolAddress((void**)&Bbuf, g_Bbuf);
    cudaGetSymbolAddress((void**)&Obuf, g_Obuf);
    cudaGetSymbolAddress((void**)&idxp, g_idxbuf);
    cudaGetSymbolAddress((void**)&pool, g_pool);
    cudaGetSymbolAddress((void**)&z1, g_z1);
    cudaGetSymbolAddress((void**)&z2, g_z2);
    cudaGetSymbolAddress((void**)&stats, g_stats);
    cudaGetSymbolAddress((void**)&ss, g_ss);

    cudaFuncSetAttribute(k_e1<64,64>,   cudaFuncAttributeMaxDynamicSharedMemorySize, (int)e1_smem(64,64));
    cudaFuncSetAttribute(k_e1<64,128>,  cudaFuncAttributeMaxDynamicSharedMemorySize, (int)e1_smem(64,128));
    cudaFuncSetAttribute(k_e1<128,256>, cudaFuncAttributeMaxDynamicSharedMemorySize, (int)e1_smem(128,256));
    cudaFuncSetAttribute(k_e3<64,64>,   cudaFuncAttributeMaxDynamicSharedMemorySize, (int)e3_smem(64));
    cudaFuncSetAttribute(k_e3<128,128>, cudaFuncAttributeMaxDynamicSharedMemorySize, (int)e3_smem(128));
    cudaFuncSetAttribute(k_e3<256,256>, cudaFuncAttributeMaxDynamicSharedMemorySize, (int)e3_smem(256));

    k_zero_stats<<<1, 256>>>(stats);

    // stage 0: input MLP
    k_in_gemm<<<256, 256>>>(x, w_in, h0, stats);
    k_finalize<<<1, 512>>>(stats, ss, ST0, 64, 1.f/ROWS, g_in, b_in);
    k_apply<<<ROWS*64/256, 256>>>(h0, ss, ST0, 64, ROWS*64);

    // conv1: C_IN=64, C_MID=64, C_OUT=64
    k_e1<64,64><<<BB, 256, e1_smem(64,64)>>>(h0, w1a, Abuf, Bbuf, idxp, stats, ST1);
    k_finalize<<<1, 512>>>(stats, ss, ST1, 64, 1.f/(ROWS*KK), g1a, b1a);
    k_e3<64,64><<<dim3(BB,1), 256, e3_smem(64)>>>(Abuf, Bbuf, idxp, w1b, ss, ST1, stats, ST2, Obuf);
    k_finalize<<<1, 512>>>(stats, ss, ST2, 64, 1.f/(ROWS*KK), g1b, b1b);
    k_apply_ec<<<ROWS*64/256, 256>>>(Obuf, h1, ss, ST2, 64, ROWS*64);

    // conv2: C_IN=64, C_MID=128, C_OUT=128
    k_e1<64,128><<<BB, 256, e1_smem(64,128)>>>(h1, w2a, Abuf, Bbuf, idxp, stats, ST3);
    k_finalize<<<1, 512>>>(stats, ss, ST3, 128, 1.f/(ROWS*KK), g2a, b2a);
    k_e3<128,128><<<dim3(BB,2), 256, e3_smem(128)>>>(Abuf, Bbuf, idxp, w2b, ss, ST3, stats, ST4, Obuf);
    k_finalize<<<1, 512>>>(stats, ss, ST4, 128, 1.f/(ROWS*KK), g2b, b2b);
    k_apply_ec<<<ROWS*128/256, 256>>>(Obuf, h2, ss, ST4, 128, ROWS*128);

    // conv3: C_IN=128, C_MID=256, C_OUT=256
    k_e1<128,256><<<BB, 256, e1_smem(128,256)>>>(h2, w3a, Abuf, Bbuf, idxp, stats, ST5);
    k_finalize<<<1, 512>>>(stats, ss, ST5, 256, 1.f/(ROWS*KK), g3a, b3a);
    k_e3<256,256><<<dim3(BB,4), 256, e3_smem(256)>>>(Abuf, Bbuf, idxp, w3b, ss, ST5, stats, ST6, Obuf);
    k_finalize<<<1, 512>>>(stats, ss, ST6, 256, 1.f/(ROWS*KK), g3b, b3b);
    k_apply_ec<<<ROWS*256/256, 256>>>(Obuf, h3, ss, ST6, 256, ROWS*256);

    // pooling + classifier
    k_pool<<<BB, 256>>>(h1, h2, h3, pool);

    k_gemm<<<dim3(512/16, BB/16), dim3(16,16)>>>(pool, wc1, nullptr, z1, BB, 896, 512, stats, ST7);
    k_finalize<<<1, 512>>>(stats, ss, ST7, 512, 1.f/BB, gc1, bc1);
    k_apply<<<BB*512/256, 256>>>(z1, ss, ST7, 512, BB*512);

    k_gemm<<<dim3(256/16, BB/16), dim3(16,16)>>>(z1, wc2, nullptr, z2, BB, 512, 256, stats, ST8);
    k_finalize<<<1, 512>>>(stats, ss, ST8, 256, 1.f/BB, gc2, bc2);
    k_apply<<<BB*256/256, 256>>>(z2, ss, ST8, 256, BB*256);

    k_gemm<<<dim3(1, BB/16), dim3(16,16)>>>(z2, wc3, bc3, out, BB, 256, 2, nullptr, 0);
}

// round 4
// speedup vs baseline: 1.1781x; 1.1781x over previous
#include <cuda_runtime.h>
#include <cuda_bf16.h>
#include <math.h>

// ------------------------- problem constants -------------------------
#define BB   512
#define NN   64
#define KK   16
#define ROWS (BB*NN)          // 32768
#define EPSV 1e-5f

// ------------------------- scratch (device globals) ------------------
__device__ float g_h0[ROWS*64];
__device__ float g_h1[ROWS*64];
__device__ float g_h2[ROWS*128];
__device__ float g_h3[ROWS*256];
__device__ float g_Abuf[ROWS*256];
__device__ float g_Bbuf[ROWS*256];
__device__ float g_Obuf[ROWS*256];
__device__ int   g_idxbuf[ROWS*KK];
__device__ float g_pool[BB*896];
__device__ float g_z1[BB*512];
__device__ float g_z2[BB*256];
__device__ float g_stats[4096];
__device__ float g_ss[4096];

// stage bases in g_stats/g_ss
#define ST0 0      // pre0   C=64
#define ST1 128    // c1 pre1 C=64
#define ST2 256    // c1 pre2 C=64
#define ST3 384    // c2 pre1 C=128
#define ST4 640    // c2 pre2 C=128
#define ST5 896    // c3 pre1 C=256
#define ST6 1408   // c3 pre2 C=256
#define ST7 1920   // zc1 C=512
#define ST8 2944   // zc2 C=256

__device__ __forceinline__ unsigned enc_f(float f) {
    unsigned u = __float_as_uint(f);
    return (u & 0x80000000u) ? ~u : (u | 0x80000000u);
}
__device__ __forceinline__ float dec_f(unsigned u) {
    return (u & 0x80000000u) ? __uint_as_float(u ^ 0x80000000u) : __uint_as_float(~u);
}
#define NEG_INF __int_as_float(0xff800000)

// ------------------------- kernels -----------------------------------

__global__ void k_zero_stats(float* stats) {
    for (int i = threadIdx.x; i < 4096; i += blockDim.x) stats[i] = 0.f;
}

// pre0 = x @ w_in  (32768x6 @ 6x64) + per-channel stats
__global__ void k_in_gemm(const float* __restrict__ x, const float* __restrict__ w,
                          float* __restrict__ pre, float* __restrict__ stats) {
    __shared__ float xs[128*6];
    __shared__ float wsm[6*64];
    __shared__ float red[4][64];
    int t = threadIdx.x;
    int r0 = blockIdx.x * 128;
    for (int e = t; e < 768; e += 256) xs[e] = x[r0*6 + e];
    for (int e = t; e < 384; e += 256) wsm[e] = w[e];
    __syncthreads();
    int m = t & 63, rg = t >> 6;
    float s = 0.f, s2 = 0.f;
    for (int r = rg; r < 128; r += 4) {
        float v = 0.f;
        #pragma unroll
        for (int k = 0; k < 6; k++) v += xs[r*6+k] * wsm[k*64+m];
        pre[(r0 + r)*64 + m] = v;
        s += v; s2 += v*v;
    }
    red[rg][m] = s; __syncthreads();
    if (rg == 0) atomicAdd(&stats[ST0 + m], red[0][m]+red[1][m]+red[2][m]+red[3][m]);
    __syncthreads();
    red[rg][m] = s2; __syncthreads();
    if (rg == 0) atomicAdd(&stats[ST0 + 64 + m], red[0][m]+red[1][m]+red[2][m]+red[3][m]);
}

__global__ void k_finalize(const float* __restrict__ stats, float* __restrict__ ss,
                           int base, int C, float invcnt,
                           const float* __restrict__ g, const float* __restrict__ b) {
    int c = blockIdx.x*blockDim.x + threadIdx.x;
    if (c >= C) return;
    float mean = stats[base + c] * invcnt;
    float var  = stats[base + C + c] * invcnt - mean*mean;
    float sc = g[c] * rsqrtf(var + EPSV);
    ss[base + c]     = sc;
    ss[base + C + c] = b[c] - mean*sc;
}

// in-place: buf = lrelu(sc*buf + sh)
__global__ void k_apply(float* __restrict__ buf, const float* __restrict__ ss,
                        int base, int C, int total) {
    int i = blockIdx.x*blockDim.x + threadIdx.x;
    if (i >= total) return;
    int c = i & (C-1);
    float v = ss[base+c]*buf[i] + ss[base+C+c];
    buf[i] = v > 0.f ? v : 0.2f*v;
}

// edge-conv epilogue: H = (O==-inf) ? 0 : lrelu(sc*O+sh)
__global__ void k_apply_ec(const float* __restrict__ O, float* __restrict__ H,
                           const float* __restrict__ ss, int base, int C, int total) {
    int i = blockIdx.x*blockDim.x + threadIdx.x;
    if (i >= total) return;
    int c = i & (C-1);
    float v = O[i];
    float r;
    if (v == NEG_INF) r = 0.f;
    else { float z = ss[base+c]*v + ss[base+C+c]; r = z > 0.f ? z : 0.2f*z; }
    H[i] = r;
}

// ----- E1: per-batch KNN + A/B factor GEMMs + pre1 stats (256 thr, low-smem) -----
template<int C_IN, int C_MID>
__global__ void k_e1(const float* __restrict__ X, const float* __restrict__ w_a,
                     float* __restrict__ gA, float* __restrict__ gB,
                     int* __restrict__ gidx, float* __restrict__ stats, int sbase)
{
    extern __shared__ float sm[];
    const int XST = C_IN + 1;
    float* Xs = sm;                         // 64*XST
    float* sq = Xs + 64*XST;                // 64
    int*   idx_s = (int*)(sq + 64);         // 1024

    int b = blockIdx.x;
    int t = threadIdx.x;
    const float* Xb = X + (size_t)b*64*C_IN;

    for (int e = t; e < 64*C_IN; e += 256) {
        int i = e / C_IN, k = e % C_IN;
        Xs[i*XST + k] = Xb[e];
    }
    __syncthreads();
    if (t < 64) {
        float s = 0.f;
        for (int k = 0; k < C_IN; k++) { float v = Xs[t*XST+k]; s += v*v; }
        sq[t] = s;
    }
    __syncthreads();

    // KNN: warp per row, iterative argmin with stable (d, index) tie-break
    {
        int w = t >> 5, l = t & 31;
        for (int i = w; i < 64; i += 8) {
            float d0 = 0.f, d1 = 0.f;
            for (int k = 0; k < C_IN; k++) {
                float xi = Xs[i*XST+k];
                d0 += xi * Xs[l*XST+k];
                d1 += xi * Xs[(l+32)*XST+k];
            }
            float my0 = sq[i] + sq[l]    - 2.f*d0;
            float my1 = sq[i] + sq[l+32] - 2.f*d1;
            for (int pick = 0; pick <= KK; pick++) {
                float dm; int jm;
                if (my0 <= my1) { dm = my0; jm = l; } else { dm = my1; jm = l+32; }
                #pragma unroll
                for (int off = 16; off; off >>= 1) {
                    float od = __shfl_xor_sync(0xffffffffu, dm, off);
                    int   oj = __shfl_xor_sync(0xffffffffu, jm, off);
                    if (od < dm || (od == dm && oj < jm)) { dm = od; jm = oj; }
                }
                if ((jm & 31) == l) { if (jm >= 32) my1 = __int_as_float(0x7f800000); else my0 = __int_as_float(0x7f800000); }
                if (pick > 0 && l == 0) {
                    idx_s[i*KK + pick - 1] = jm;
                    gidx[((size_t)b*64 + i)*KK + pick - 1] = jm;
                }
            }
        }
    }
    __syncthreads();

    // A = X@Wd, B = X@(Wn-Wd)  -> global only
    {
        const int G = 256 / C_MID;
        const int IPG = 64 / G;
        int m = t % C_MID;
        int g = t / C_MID;
        for (int i0 = g*IPG; i0 < (g+1)*IPG; i0 += 8) {
            float aa[8], bb[8];
            #pragma unroll
            for (int ii = 0; ii < 8; ii++) { aa[ii]=0.f; bb[ii]=0.f; }
            for (int k = 0; k < C_IN; k++) {
                float wn  = w_a[k*C_MID + m];
                float wd  = w_a[(C_IN + k)*C_MID + m];
                float wnd = wn - wd;
                #pragma unroll
                for (int ii = 0; ii < 8; ii++) {
                    float xv = Xs[(i0+ii)*XST + k];
                    aa[ii] += xv * wd;
                    bb[ii] += xv * wnd;
                }
            }
            #pragma unroll
            for (int ii = 0; ii < 8; ii++) {
                gA[((size_t)b*64 + i0+ii)*C_MID + m] = aa[ii];
                gB[((size_t)b*64 + i0+ii)*C_MID + m] = bb[ii];
            }
        }
    }
    __syncthreads();   // make gA/gB writes visible block-wide

    // stats of pre1 = A[c] + B[idx[c,k]]  (read back from global)
    {
        const float* Ab = gA + (size_t)b*64*C_MID;
        const float* Bb = gB + (size_t)b*64*C_MID;
        const int G = 256 / C_MID;
        int m = t % C_MID, rep = t / C_MID;
        float s = 0.f, s2 = 0.f;
        for (int r = rep; r < 64*KK; r += G) {
            int c = r >> 4;
            int nbr = idx_s[r];
            float v = Ab[c*C_MID + m] + Bb[nbr*C_MID + m];
            s += v; s2 += v*v;
        }
        atomicAdd(&stats[sbase + m], s);
        atomicAdd(&stats[sbase + C_MID + m], s2);
    }
}

// ----- E3: build h rows, GEMM with w_b from L1/L2, scatter-max + pre2 stats -----
template<int C_MID, int C_OUT>
__global__ void k_e3(const float* __restrict__ gA, const float* __restrict__ gB,
                     const int* __restrict__ gidx, const float* __restrict__ w_b,
                     const float* __restrict__ ss, int ssbase,
                     float* __restrict__ stats, int sbase,
                     float* __restrict__ O)
{
    extern __shared__ float sm[];
    const int HST = C_MID + 1;
    float* Hs  = sm;                        // 32*HST
    float* scs = Hs + 32*HST;               // C_MID
    float* shs = scs + C_MID;               // C_MID
    unsigned* outu = (unsigned*)(shs + C_MID);  // 4096
    int* idx_s = (int*)(outu + 4096);           // 1024

    int b  = blockIdx.x;
    int cb = blockIdx.y * 64;
    int t  = threadIdx.x;

    for (int e = t; e < 1024; e += 256) idx_s[e] = gidx[b*1024 + e];
    for (int e = t; e < C_MID; e += 256) {
        scs[e] = ss[ssbase + e];
        shs[e] = ss[ssbase + C_MID + e];
    }
    for (int e = t; e < 4096; e += 256) outu[e] = 0u;
    __syncthreads();

    const float* Ab = gA + (size_t)b*64*C_MID;
    const float* Bb = gB + (size_t)b*64*C_MID;
    const float4* Wg = (const float4*)(w_b + cb);   // row stride C_OUT/4 float4s
    const int WS = C_OUT >> 2;

    int cg = t & 15;
    int rg = t >> 4;
    int c0 = cg * 4;
    float csum[4] = {0,0,0,0}, csq[4] = {0,0,0,0};

    for (int tt = 0; tt < 32; tt++) {
        for (int e = t; e < 32*C_MID; e += 256) {
            int rr = e / C_MID, m = e % C_MID;
            int r = tt*32 + rr;
            int c = r >> 4;
            int nbr = idx_s[r];
            float v = Ab[c*C_MID + m] + Bb[nbr*C_MID + m];
            v = scs[m]*v + shs[m];
            Hs[rr*HST + m] = v > 0.f ? v : 0.2f*v;
        }
        __syncthreads();
        int rr0 = rg*2, rr1 = rr0 + 1;
        float a00=0,a01=0,a02=0,a03=0,a10=0,a11=0,a12=0,a13=0;
        for (int kk = 0; kk < C_MID; kk++) {
            float h0 = Hs[rr0*HST + kk];
            float h1 = Hs[rr1*HST + kk];
            float4 wv = __ldg(&Wg[kk*WS + cg]);
            a00 += h0*wv.x; a01 += h0*wv.y; a02 += h0*wv.z; a03 += h0*wv.w;
            a10 += h1*wv.x; a11 += h1*wv.y; a12 += h1*wv.z; a13 += h1*wv.w;
        }
        {
            int r = tt*32 + rr0;
            int n = idx_s[r];
            csum[0]+=a00; csq[0]+=a00*a00; atomicMax(&outu[n*64+c0+0], enc_f(a00));
            csum[1]+=a01; csq[1]+=a01*a01; atomicMax(&outu[n*64+c0+1], enc_f(a01));
            csum[2]+=a02; csq[2]+=a02*a02; atomicMax(&outu[n*64+c0+2], enc_f(a02));
            csum[3]+=a03; csq[3]+=a03*a03; atomicMax(&outu[n*64+c0+3], enc_f(a03));
            r = tt*32 + rr1;
            n = idx_s[r];
            csum[0]+=a10; csq[0]+=a10*a10; atomicMax(&outu[n*64+c0+0], enc_f(a10));
            csum[1]+=a11; csq[1]+=a11*a11; atomicMax(&outu[n*64+c0+1], enc_f(a11));
            csum[2]+=a12; csq[2]+=a12*a12; atomicMax(&outu[n*64+c0+2], enc_f(a12));
            csum[3]+=a13; csq[3]+=a13*a13; atomicMax(&outu[n*64+c0+3], enc_f(a13));
        }
        __syncthreads();
    }
    #pragma unroll
    for (int j = 0; j < 4; j++) {
        atomicAdd(&stats[sbase + cb + c0 + j], csum[j]);
        atomicAdd(&stats[sbase + C_OUT + cb + c0 + j], csq[j]);
    }
    // last in-loop __syncthreads ordered all scatters
    for (int e = t; e < 4096; e += 256) {
        unsigned u = outu[e];
        float v = u ? dec_f(u) : NEG_INF;
        int n = e >> 6, j = e & 63;
        O[((size_t)b*64 + n)*C_OUT + cb + j] = v;
    }
}

// pooled = [mean_n h, max_n h], h = concat(h1,h2,h3)
__global__ void k_pool(const float* __restrict__ h1, const float* __restrict__ h2,
                       const float* __restrict__ h3, float* __restrict__ pool) {
    int b = blockIdx.x, t = threadIdx.x;
    for (int ch = t; ch < 448; ch += 256) {
        const float* src; int C, cc;
        if (ch < 64)       { src = h1; C = 64;  cc = ch; }
        else if (ch < 192) { src = h2; C = 128; cc = ch - 64; }
        else               { src = h3; C = 256; cc = ch - 192; }
        float s = 0.f, mx = NEG_INF;
        for (int n = 0; n < 64; n++) {
            float v = src[((size_t)b*64 + n)*C + cc];
            s += v; mx = fmaxf(mx, v);
        }
        pool[b*896 + ch]       = s * (1.f/64.f);
        pool[b*896 + 448 + ch] = mx;
    }
}

// classifier GEMM (tiled 16x16), optional bias, optional column stats
__global__ void k_gemm(const float* __restrict__ A, const float* __restrict__ W,
                       const float* __restrict__ bias, float* __restrict__ Cout,
                       int M, int Kd, int Nn, float* stats, int sbase) {
    __shared__ float as[16][17], ws[16][17];
    int tx = threadIdx.x, ty = threadIdx.y;
    int row = blockIdx.y*16 + ty;
    int col = blockIdx.x*16 + tx;
    float acc = 0.f;
    for (int k0 = 0; k0 < Kd; k0 += 16) {
        as[ty][tx] = (row < M && k0+tx < Kd) ? A[row*Kd + k0 + tx] : 0.f;
        ws[ty][tx] = (k0+ty < Kd && col < Nn) ? W[(k0+ty)*Nn + col] : 0.f;
        __syncthreads();
        #pragma unroll
        for (int kk = 0; kk < 16; kk++) acc += as[ty][kk]*ws[kk][tx];
        __syncthreads();
    }
    if (row < M && col < Nn) {
        if (bias) acc += bias[col];
        Cout[row*Nn + col] = acc;
        if (stats) {
            atomicAdd(&stats[sbase + col], acc);
            atomicAdd(&stats[sbase + Nn + col], acc*acc);
        }
    }
}

// ------------------------- host launcher -----------------------------
static inline size_t e1_smem(int cin) {
    return (size_t)(64*(cin+1) + 64)*4 + 1024*4;
}
static inline size_t e3_smem(int cmid) {
    return (size_t)(32*(cmid+1) + 2*cmid)*4 + 4096*4 + 1024*4;
}

extern "C" void kernel_launch(void* const* d_in, const int* in_sizes, int n_in,
                              void* d_out, int out_size) {
    static const int ALPHA[31] = {30,7,26,17,6,20,11,0,21,12,1,22,13,2,23,14,3,
                                  24,15,4,25,16,5,27,18,8,28,19,9,29,10};
    const void* in[31];
    bool refOrder = (in_sizes[0] == ROWS*6);
    for (int i = 0; i < 31; i++) in[i] = refOrder ? d_in[i] : d_in[ALPHA[i]];

    const float* x    = (const float*)in[0];
    const float* w_in = (const float*)in[2];
    const float* g_in = (const float*)in[3];
    const float* b_in = (const float*)in[4];
    const float* w1a  = (const float*)in[5];
    const float* g1a  = (const float*)in[6];
    const float* b1a  = (const float*)in[7];
    const float* w1b  = (const float*)in[8];
    const float* g1b  = (const float*)in[9];
    const float* b1b  = (const float*)in[10];
    const float* w2a  = (const float*)in[11];
    const float* g2a  = (const float*)in[12];
    const float* b2a  = (const float*)in[13];
    const float* w2b  = (const float*)in[14];
    const float* g2b  = (const float*)in[15];
    const float* b2b  = (const float*)in[16];
    const float* w3a  = (const float*)in[17];
    const float* g3a  = (const float*)in[18];
    const float* b3a  = (const float*)in[19];
    const float* w3b  = (const float*)in[20];
    const float* g3b  = (const float*)in[21];
    const float* b3b  = (const float*)in[22];
    const float* wc1  = (const float*)in[23];
    const float* gc1  = (const float*)in[24];
    const float* bc1  = (const float*)in[25];
    const float* wc2  = (const float*)in[26];
    const float* gc2  = (const float*)in[27];
    const float* bc2  = (const float*)in[28];
    const float* wc3  = (const float*)in[29];
    const float* bc3  = (const float*)in[30];
    float* out = (float*)d_out;

    float *h0, *h1, *h2, *h3, *Abuf, *Bbuf, *Obuf, *pool, *z1, *z2, *stats, *ss;
    int* idxp;
    cudaGetSymbolAddress((void**)&h0, g_h0);
    cudaGetSymbolAddress((void**)&h1, g_h1);
    cudaGetSymbolAddress((void**)&h2, g_h2);
    cudaGetSymbolAddress((void**)&h3, g_h3);
    cudaGetSymbolAddress((void**)&Abuf, g_Abuf);
    cudaGetSymbolAddress((void**)&Bbuf, g_Bbuf);
    cudaGetSymbolAddress((void**)&Obuf, g_Obuf);
    cudaGetSymbolAddress((void**)&idxp, g_idxbuf);
    cudaGetSymbolAddress((void**)&pool, g_pool);
    cudaGetSymbolAddress((void**)&z1, g_z1);
    cudaGetSymbolAddress((void**)&z2, g_z2);
    cudaGetSymbolAddress((void**)&stats, g_stats);
    cudaGetSymbolAddress((void**)&ss, g_ss);

    cudaFuncSetAttribute(k_e1<64,64>,   cudaFuncAttributeMaxDynamicSharedMemorySize, (int)e1_smem(64));
    cudaFuncSetAttribute(k_e1<64,128>,  cudaFuncAttributeMaxDynamicSharedMemorySize, (int)e1_smem(64));
    cudaFuncSetAttribute(k_e1<128,256>, cudaFuncAttributeMaxDynamicSharedMemorySize, (int)e1_smem(128));
    cudaFuncSetAttribute(k_e3<64,64>,   cudaFuncAttributeMaxDynamicSharedMemorySize, (int)e3_smem(64));
    cudaFuncSetAttribute(k_e3<128,128>, cudaFuncAttributeMaxDynamicSharedMemorySize, (int)e3_smem(128));
    cudaFuncSetAttribute(k_e3<256,256>, cudaFuncAttributeMaxDynamicSharedMemorySize, (int)e3_smem(256));

    k_zero_stats<<<1, 256>>>(stats);

    // stage 0: input MLP
    k_in_gemm<<<256, 256>>>(x, w_in, h0, stats);
    k_finalize<<<1, 512>>>(stats, ss, ST0, 64, 1.f/ROWS, g_in, b_in);
    k_apply<<<ROWS*64/256, 256>>>(h0, ss, ST0, 64, ROWS*64);

    // conv1: C_IN=64, C_MID=64, C_OUT=64
    k_e1<64,64><<<BB, 256, e1_smem(64)>>>(h0, w1a, Abuf, Bbuf, idxp, stats, ST1);
    k_finalize<<<1, 512>>>(stats, ss, ST1, 64, 1.f/(ROWS*KK), g1a, b1a);
    k_e3<64,64><<<dim3(BB,1), 256, e3_smem(64)>>>(Abuf, Bbuf, idxp, w1b, ss, ST1, stats, ST2, Obuf);
    k_finalize<<<1, 512>>>(stats, ss, ST2, 64, 1.f/(ROWS*KK), g1b, b1b);
    k_apply_ec<<<ROWS*64/256, 256>>>(Obuf, h1, ss, ST2, 64, ROWS*64);

    // conv2: C_IN=64, C_MID=128, C_OUT=128
    k_e1<64,128><<<BB, 256, e1_smem(64)>>>(h1, w2a, Abuf, Bbuf, idxp, stats, ST3);
    k_finalize<<<1, 512>>>(stats, ss, ST3, 128, 1.f/(ROWS*KK), g2a, b2a);
    k_e3<128,128><<<dim3(BB,2), 256, e3_smem(128)>>>(Abuf, Bbuf, idxp, w2b, ss, ST3, stats, ST4, Obuf);
    k_finalize<<<1, 512>>>(stats, ss, ST4, 128, 1.f/(ROWS*KK), g2b, b2b);
    k_apply_ec<<<ROWS*128/256, 256>>>(Obuf, h2, ss, ST4, 128, ROWS*128);

    // conv3: C_IN=128, C_MID=256, C_OUT=256
    k_e1<128,256><<<BB, 256, e1_smem(128)>>>(h2, w3a, Abuf, Bbuf, idxp, stats, ST5);
    k_finalize<<<1, 512>>>(stats, ss, ST5, 256, 1.f/(ROWS*KK), g3a, b3a);
    k_e3<256,256><<<dim3(BB,4), 256, e3_smem(256)>>>(Abuf, Bbuf, idxp, w3b, ss, ST5, stats, ST6, Obuf);
    k_finalize<<<1, 512>>>(stats, ss, ST6, 256, 1.f/(ROWS*KK), g3b, b3b);
    k_apply_ec<<<ROWS*256/256, 256>>>(Obuf, h3, ss, ST6, 256, ROWS*256);

    // pooling + classifier
    k_pool<<<BB, 256>>>(h1, h2, h3, pool);

    k_gemm<<<dim3(512/16, BB/16), dim3(16,16)>>>(pool, wc1, nullptr, z1, BB, 896, 512, stats, ST7);
    k_finalize<<<1, 512>>>(stats, ss, ST7, 512, 1.f/BB, gc1, bc1);
    k_apply<<<BB*512/256, 256>>>(z1, ss, ST7, 512, BB*512);

    k_gemm<<<dim3(256/16, BB/16), dim3(16,16)>>>(z1, wc2, nullptr, z2, BB, 512, 256, stats, ST8);
    k_finalize<<<1, 512>>>(stats, ss, ST8, 256, 1.f/BB, gc2, bc2);
    k_apply<<<BB*256/256, 256>>>(z2, ss, ST8, 256, BB*256);

    k_gemm<<<dim3(1, BB/16), dim3(16,16)>>>(z2, wc3, bc3, out, BB, 256, 2, nullptr, 0);
}